// round 16
// baseline (speedup 1.0000x reference)
#include <cuda_runtime.h>
#include <cuda_fp16.h>
#include <cstdint>

// ============================================================================
// SelfAttention R16: single-pass fp16 HMMA, CTA tile 256x128 with 16 warps
// (warp tile 64x32). LDSM bytes/MAC x0.75 vs R15 (6 ldsm : 16 MMA instead of
// 4 : 8) -> smem crossbar no longer binding; tensor pipe becomes the floor.
// Same numerics as R15 (rel_err 4.9e-4). 512 thr, K-chunk 64, 3-stage
// cp.async, fused QKV launch, shuffle softmax.
// ============================================================================

constexpr int S = 2048, D = 1024, NB = 4;
constexpr long SD  = (long)S * D;
constexpr long SSZ = (long)S * S;
constexpr long NX = (long)NB * S * D;
constexpr long NW = (long)D * D;
constexpr long NP = (long)NB * S * S;

constexpr long OXH  = 0;
constexpr long OWQH = NX, OWKH = NX + NW, OWVH = NX + 2 * NW;
constexpr long OQH  = NX + 3 * NW;
constexpr long OKH  = OQH + NX;
constexpr long OVTH = OQH + 2 * NX;
constexpr long OPH  = OQH + 3 * NX;
constexpr long NHF  = OPH + NP;

__device__ __align__(128) __half g_hf[NHF];
__device__ float g_sc[NP];

constexpr int STAGE = 48 * 1024;           // A 32KB (256 rows) | B 16KB (128)
constexpr int OFF_B = 32768;
constexpr int NSTG  = 3;
constexpr int SMEM_DYN = NSTG * STAGE + 1024;   // 148,480

#define SWZ(o) ((o) ^ (((o) >> 3) & 0x70))

// ---------------------------------------------------------------- helpers
__device__ __forceinline__ uint32_t smem_u32(const void* p) {
    uint32_t a;
    asm("{ .reg .u64 t; cvta.to.shared.u64 t, %1; cvt.u32.u64 %0, t; }"
        : "=r"(a) : "l"(p));
    return a;
}
__device__ __forceinline__ void ldsm4(uint32_t* r, uint32_t addr) {
    asm volatile("ldmatrix.sync.aligned.m8n8.x4.shared.b16 {%0,%1,%2,%3}, [%4];"
                 : "=r"(r[0]), "=r"(r[1]), "=r"(r[2]), "=r"(r[3]) : "r"(addr));
}
__device__ __forceinline__ void mma_f16(float* d, const uint32_t* a,
                                        const uint32_t* b) {
    asm volatile(
        "mma.sync.aligned.m16n8k16.row.col.f32.f16.f16.f32 "
        "{%0,%1,%2,%3}, {%4,%5,%6,%7}, {%8,%9}, {%0,%1,%2,%3};"
        : "+f"(d[0]), "+f"(d[1]), "+f"(d[2]), "+f"(d[3])
        : "r"(a[0]), "r"(a[1]), "r"(a[2]), "r"(a[3]), "r"(b[0]), "r"(b[1]));
}
#define CPA16(dst, src) \
    asm volatile("cp.async.cg.shared.global [%0], [%1], 16;" \
                 :: "r"(dst), "l"(src) : "memory")
#define CP_COMMIT() asm volatile("cp.async.commit_group;" ::: "memory")

__device__ __forceinline__ uint32_t pack2h(float v0, float v1) {
    __half2 hh = __halves2half2(__float2half_rn(v0), __float2half_rn(v1));
    return *reinterpret_cast<uint32_t*>(&hh);
}

// ---------------------------------------------------------------- converter
__global__ void __launch_bounds__(256)
conv_all(const float* __restrict__ x, const float* __restrict__ wq,
         const float* __restrict__ wk, const float* __restrict__ wv)
{
    const long i = ((long)blockIdx.x * 256 + threadIdx.x) * 4;
    const long total = NX + 3 * NW;
    if (i >= total) return;
    const float* src;
    long loc = i;
    if (i < NX)               { src = x; }
    else if (i < NX + NW)     { src = wq; loc = i - NX; }
    else if (i < NX + 2 * NW) { src = wk; loc = i - NX - NW; }
    else                      { src = wv; loc = i - NX - 2 * NW; }
    float4 v = *reinterpret_cast<const float4*>(src + loc);
    uint2 h;
    h.x = pack2h(v.x, v.y);
    h.y = pack2h(v.z, v.w);
    *reinterpret_cast<uint2*>(&g_hf[0] + i) = h;
}

// ---------------------------------------------------------------- mainloop
// 512 thr, 16 warps (4m x 4n), warp tile 64x32, CTA 256x128, K-chunk 64.
// Per ks per warp: 4 A-ldsm + 2 B-ldsm, 16 HMMA. acc[64].
__device__ __forceinline__ void gemm_mainloop(
    const __half* __restrict__ gA, const __half* __restrict__ gB,
    int lda, int ldb, int K, uint32_t abase, float* acc)
{
    const int tid = threadIdx.x, lane = tid & 31, wid = tid >> 5;

    // A loader: row ra = tid>>1 (0..255), seg group (tid&1)*4, 4 x 16B
    const int ra = tid >> 1, sa = (tid & 1) * 4;
    uint32_t aoff[4];
#pragma unroll
    for (int q = 0; q < 4; q++)
        aoff[q] = SWZ((uint32_t)ra * 128 + (sa + q) * 16);
    const __half* pA = gA + (long)ra * lda + sa * 8;
    // B loader: row rb = tid>>2 (0..127), seg group (tid&3)*2, 2 x 16B
    const int rb = tid >> 2, sbq = (tid & 3) * 2;
    uint32_t boff[2];
#pragma unroll
    for (int q = 0; q < 2; q++)
        boff[q] = OFF_B + SWZ((uint32_t)rb * 128 + (sbq + q) * 16);
    const __half* pB = gB + (long)rb * ldb + sbq * 8;

    // fragment constants: warp tile 64(m) x 32(n) at (mw, nw)
    const int mw = (wid >> 2) * 64, nw = (wid & 3) * 32;
    uint32_t a_row[4], a_swz[4];
#pragma unroll
    for (int i = 0; i < 4; i++) {
        const uint32_t rbb = (uint32_t)(mw + 16 * i + (lane & 15)) * 128;
        a_row[i] = rbb; a_swz[i] = (rbb >> 3) & 0x70;
    }
    const uint32_t a_kl = (uint32_t)((lane >> 4) << 4);
    uint32_t b_row[2], b_swz[2];
#pragma unroll
    for (int p = 0; p < 2; p++) {
        const uint32_t rbb =
            (uint32_t)(nw + 16 * p + (lane & 7) + ((lane & 16) >> 1)) * 128;
        b_row[p] = rbb; b_swz[p] = (rbb >> 3) & 0x70;
    }
    const uint32_t b_kl = (uint32_t)((lane & 8) << 1);

    const int nch = K >> 6;

#define ISSUE(ch) do {                                                        \
        const uint32_t _sb = abase + (uint32_t)((ch) % NSTG) * STAGE;         \
        const long _k = (long)(ch) * 64;                                      \
        _Pragma("unroll")                                                     \
        for (int q = 0; q < 4; q++) CPA16(_sb + aoff[q], pA + _k + q * 8);    \
        _Pragma("unroll")                                                     \
        for (int q = 0; q < 2; q++) CPA16(_sb + boff[q], pB + _k + q * 8);    \
        CP_COMMIT();                                                          \
    } while (0)

    ISSUE(0);
    ISSUE(1);

    for (int ch = 0; ch < nch; ch++) {
        if (ch + 1 < nch)
            asm volatile("cp.async.wait_group 1;" ::: "memory");
        else
            asm volatile("cp.async.wait_group 0;" ::: "memory");
        __syncthreads();
        if (ch + 2 < nch) ISSUE(ch + 2);

        const uint32_t sb = abase + (uint32_t)(ch % NSTG) * STAGE;
#pragma unroll
        for (int ks = 0; ks < 4; ks++) {
            const uint32_t KB = ks * 32;
            uint32_t af[4][4], bf[8];
#pragma unroll
            for (int i = 0; i < 4; i++)
                ldsm4(af[i], sb + a_row[i] + ((KB + a_kl) ^ a_swz[i]));
#pragma unroll
            for (int p = 0; p < 2; p++)
                ldsm4(&bf[4 * p], sb + OFF_B + b_row[p] +
                                  ((KB + b_kl) ^ b_swz[p]));
#pragma unroll
            for (int i = 0; i < 4; i++)
#pragma unroll
                for (int j = 0; j < 4; j++)
                    mma_f16(acc + (i * 4 + j) * 4, af[i], &bf[j * 2]);
        }
    }
#undef ISSUE
}

// ---------------------------------------------------------------- fused QKV
// grid (D/128, NB*S/256, 3): z=0 Q, z=1 K (row-major fp16), z=2 VT
// (per-batch transposed fp16, ld=S, smem-staged). CTA tile 256x128.
__global__ void __launch_bounds__(512, 1)
mma_qkv(const float* __restrict__ bq, const float* __restrict__ bk,
        const float* __restrict__ bv)
{
    const int z = blockIdx.z;
    const long row0 = (long)blockIdx.y * 256, col0 = (long)blockIdx.x * 128;

    extern __shared__ char smem_raw[];
    const uint32_t rawb  = smem_u32(smem_raw);
    const uint32_t abase = (rawb + 1023) & ~1023u;
    char* smem = smem_raw + (abase - rawb);

    const __half* W = &g_hf[z == 0 ? OWQH : z == 1 ? OWKH : OWVH];
    const float* bias = z == 0 ? bq : z == 1 ? bk : bv;

    float acc[64];
#pragma unroll
    for (int i = 0; i < 64; i++) acc[i] = 0.f;

    gemm_mainloop(&g_hf[OXH] + row0 * D, W + col0 * D, D, D, D, abase, acc);

    const int tid = threadIdx.x, lane = tid & 31, wid = tid >> 5;
    const int mw = (wid >> 2) * 64, nw = (wid & 3) * 32;
    const int qr = lane >> 2, qc = lane & 3;

    if (z < 2) {
        __half* Ch = &g_hf[z == 0 ? OQH : OKH];
#pragma unroll
        for (int i = 0; i < 4; i++)
#pragma unroll
            for (int j = 0; j < 4; j++) {
                const float* d = acc + (i * 4 + j) * 4;
#pragma unroll
                for (int h = 0; h < 2; h++) {
                    const long r = row0 + mw + 16 * i + qr + 8 * h;
                    const long c = col0 + nw + 8 * j + 2 * qc;
                    *reinterpret_cast<uint32_t*>(&Ch[r * D + c]) =
                        pack2h(d[2 * h] + bias[c], d[2 * h + 1] + bias[c + 1]);
                }
            }
    } else {
        // VT: stage transposed 256-row x 128-col tile in smem (stride 264),
        // then coalesced 16B stores along the row (m) direction.
        const long b = row0 >> 11, rloc = row0 & (S - 1);
        __half* Ch = &g_hf[OVTH] + b * SD;
        __syncthreads();
        __half* sh = reinterpret_cast<__half*>(smem);
#pragma unroll
        for (int i = 0; i < 4; i++)
#pragma unroll
            for (int j = 0; j < 4; j++) {
                const float* d = acc + (i * 4 + j) * 4;
#pragma unroll
                for (int h = 0; h < 2; h++) {
                    const int rl = mw + 16 * i + qr + 8 * h;
                    const int cl = nw + 8 * j + 2 * qc;
                    sh[cl * 264 + rl] =
                        __float2half_rn(d[2 * h] + bias[col0 + cl]);
                    sh[(cl + 1) * 264 + rl] =
                        __float2half_rn(d[2 * h + 1] + bias[col0 + cl + 1]);
                }
            }
        __syncthreads();
        const int c = tid >> 2, seg = tid & 3;   // 128 cols x 4 segs of 64 elems
        const __half* sr = sh + c * 264 + seg * 64;
        __half* ds = Ch + (col0 + c) * (long)S + rloc + seg * 64;
#pragma unroll
        for (int q = 0; q < 8; q++)
            *reinterpret_cast<uint4*>(ds + q * 8) =
                *reinterpret_cast<const uint4*>(sr + q * 8);
    }
}

// ---------------------------------------------------------------- generic GEMM
// fp32 out: Cf[r*ldc + c] = scale * A@B^T. Batched by blockIdx.z. 256x128 tile.
__global__ void __launch_bounds__(512, 1)
mma_gemm(const __half* __restrict__ A, const __half* __restrict__ B,
         float* __restrict__ Cf, int K, int lda, int ldb, int ldc,
         long sA, long sB, long sC, float scale)
{
    const long zb = blockIdx.z;
    const long row0 = (long)blockIdx.y * 256, col0 = (long)blockIdx.x * 128;

    extern __shared__ char smem_raw[];
    const uint32_t rawb  = smem_u32(smem_raw);
    const uint32_t abase = (rawb + 1023) & ~1023u;

    float acc[64];
#pragma unroll
    for (int i = 0; i < 64; i++) acc[i] = 0.f;

    gemm_mainloop(A + sA * zb + row0 * (long)lda,
                  B + sB * zb + col0 * (long)ldb, lda, ldb, K, abase, acc);

    float* Cp = Cf + sC * zb;
    const int tid = threadIdx.x, lane = tid & 31, wid = tid >> 5;
    const int mw = (wid >> 2) * 64, nw = (wid & 3) * 32;
    const int qr = lane >> 2, qc = lane & 3;
#pragma unroll
    for (int i = 0; i < 4; i++)
#pragma unroll
        for (int j = 0; j < 4; j++) {
            const float* d = acc + (i * 4 + j) * 4;
#pragma unroll
            for (int h = 0; h < 2; h++) {
                const long r = row0 + mw + 16 * i + qr + 8 * h;
                const long c = col0 + nw + 8 * j + 2 * qc;
                *reinterpret_cast<float2*>(&Cp[r * (long)ldc + c]) =
                    make_float2(d[2 * h] * scale, d[2 * h + 1] * scale);
            }
        }
}

// ---------------------------------------------------------------- softmax
__global__ void __launch_bounds__(256)
softmax_rows(const float* __restrict__ sc, __half* __restrict__ ph)
{
    const long ro = (long)blockIdx.x * 2048;
    const float* p = sc + ro;
    __shared__ float red[8];
    const int t = threadIdx.x, lane = t & 31, w = t >> 5;

    float v[8];
    *reinterpret_cast<float4*>(v)     = *reinterpret_cast<const float4*>(p + t * 8);
    *reinterpret_cast<float4*>(v + 4) = *reinterpret_cast<const float4*>(p + t * 8 + 4);

    float m = v[0];
#pragma unroll
    for (int i = 1; i < 8; i++) m = fmaxf(m, v[i]);
#pragma unroll
    for (int o = 16; o > 0; o >>= 1)
        m = fmaxf(m, __shfl_xor_sync(0xffffffffu, m, o));
    if (lane == 0) red[w] = m;
    __syncthreads();
    m = red[lane & 7];
#pragma unroll
    for (int o = 4; o > 0; o >>= 1)
        m = fmaxf(m, __shfl_xor_sync(0xffffffffu, m, o));

    float sum = 0.f;
#pragma unroll
    for (int i = 0; i < 8; i++) { v[i] = __expf(v[i] - m); sum += v[i]; }
#pragma unroll
    for (int o = 16; o > 0; o >>= 1)
        sum += __shfl_xor_sync(0xffffffffu, sum, o);
    __syncthreads();
    if (lane == 0) red[w] = sum;
    __syncthreads();
    sum = red[lane & 7];
#pragma unroll
    for (int o = 4; o > 0; o >>= 1)
        sum += __shfl_xor_sync(0xffffffffu, sum, o);
    const float inv = 1.f / sum;

    uint32_t hh[4];
#pragma unroll
    for (int i = 0; i < 4; i++)
        hh[i] = pack2h(v[2 * i] * inv, v[2 * i + 1] * inv);
    *reinterpret_cast<uint4*>(ph + ro + t * 8) =
        make_uint4(hh[0], hh[1], hh[2], hh[3]);
}

// ---------------------------------------------------------------- launch
extern "C" void kernel_launch(void* const* d_in, const int* in_sizes, int n_in,
                              void* d_out, int out_size)
{
    const float* x  = (const float*)d_in[0];
    const float* Wq = (const float*)d_in[1];
    const float* bq = (const float*)d_in[2];
    const float* Wk = (const float*)d_in[3];
    const float* bk = (const float*)d_in[4];
    const float* Wv = (const float*)d_in[5];
    const float* bv = (const float*)d_in[6];
    float* out = (float*)d_out;

    __half* hf; float* scp;
    cudaGetSymbolAddress((void**)&hf, g_hf);
    cudaGetSymbolAddress((void**)&scp, g_sc);

    cudaFuncSetAttribute(mma_qkv, cudaFuncAttributeMaxDynamicSharedMemorySize,
                         SMEM_DYN);
    cudaFuncSetAttribute(mma_gemm, cudaFuncAttributeMaxDynamicSharedMemorySize,
                         SMEM_DYN);
    dim3 thr(512);

    // launch 1: merged fp16 converter
    const long tot = NX + 3 * NW;
    conv_all<<<(int)((tot / 4 + 255) / 256), 256>>>(x, Wq, Wk, Wv);

    // launch 2: fused Q/K/VT projections (256x128 tiles)
    dim3 g_qkv(D / 128, (NB * S) / 256, 3);
    mma_qkv<<<g_qkv, thr, SMEM_DYN>>>(bq, bk, bv);

    // launch 3: Sc = Q@K^T / 32 (fp32), batched
    dim3 g_sc(S / 128, S / 256, NB);
    mma_gemm<<<g_sc, thr, SMEM_DYN>>>(hf + OQH, hf + OKH,
                                      scp, D, D, D, S, SD, SD, SSZ, 0.03125f);

    // launch 4: softmax -> P fp16
    softmax_rows<<<NB * S, 256>>>(scp, hf + OPH);

    // launch 5: O = P@VT^T (fp32), batched, K = S
    dim3 g_o(D / 128, S / 256, NB);
    mma_gemm<<<g_o, thr, SMEM_DYN>>>(hf + OPH, hf + OVTH,
                                     out, S, S, S, D, SSZ, SD, SD, 1.f);
}